// round 16
// baseline (speedup 1.0000x reference)
#include <cuda_runtime.h>
#include <cuda_fp16.h>
#include <cstdint>
#include <cstddef>

// ---------------- problem constants ----------------
#define BS 8192
#define DIM 1024
#define INV_T 10.0f          // 1 / TEMPERATURE
#define MARGIN 1.0f          // max(0.01, 1.0 - 0.1*0.0)

// ---------------- GEMM tiling (R2 exact) ----------------
#define BM 128
#define BN 128
#define BK 64
#define NSTAGE 3
#define NKCH (DIM / BK)                 // 16 K-chunks
#define A_ST (BM * BK * 2)              // 16384 B / stage
#define B_ST (BN * BK * 2)              // 16384 B / stage
#define STAGE_BYTES (A_ST + B_ST)       // 32768
#define DATA_BYTES (STAGE_BYTES * NSTAGE)  // 98304
#define SMEM_TOTAL (DATA_BYTES + 1024)
#define TOTAL_CTAS ((BS / BM) * (BS / BN))   // 4096

// ---------------- device scratch (no allocation allowed) ----------------
__device__ __align__(16) __half   g_A[BS * DIM];     // normalized anchor, fp16
__device__ __align__(16) __half   g_Nn[BS * DIM];    // normalized negative, fp16
__device__ float    g_pos[BS];                       // positive distance / T
__device__ unsigned g_rowmax[BS];                    // encoded row-max of dot
__device__ unsigned g_done;                          // CTA completion counter

// ---------------- helpers ----------------
__device__ __forceinline__ uint32_t smem_u32(const void* p) {
    uint32_t a;
    asm("{ .reg .u64 t; cvta.to.shared.u64 t, %1; cvt.u32.u64 %0, t; }"
        : "=r"(a) : "l"(p));
    return a;
}

__device__ __forceinline__ void cp_async16(uint32_t s, const void* g) {
    asm volatile("cp.async.cg.shared.global [%0], [%1], 16;" :: "r"(s), "l"(g));
}
#define CP_COMMIT() asm volatile("cp.async.commit_group;" ::: "memory")
#define CP_WAIT2()  asm volatile("cp.async.wait_group 2;" ::: "memory")

__device__ __forceinline__ void ldsm_x4(uint32_t addr, uint32_t& r0, uint32_t& r1,
                                        uint32_t& r2, uint32_t& r3) {
    asm volatile("ldmatrix.sync.aligned.m8n8.x4.shared.b16 {%0,%1,%2,%3}, [%4];"
                 : "=r"(r0), "=r"(r1), "=r"(r2), "=r"(r3) : "r"(addr));
}

__device__ __forceinline__ void mma16816(float* c, const uint32_t* a,
                                         uint32_t b0, uint32_t b1) {
    asm volatile(
        "mma.sync.aligned.m16n8k16.row.col.f32.f16.f16.f32 "
        "{%0,%1,%2,%3}, {%4,%5,%6,%7}, {%8,%9}, {%0,%1,%2,%3};"
        : "+f"(c[0]), "+f"(c[1]), "+f"(c[2]), "+f"(c[3])
        : "r"(a[0]), "r"(a[1]), "r"(a[2]), "r"(a[3]), "r"(b0), "r"(b1));
}

__device__ __forceinline__ uint32_t swz(uint32_t off) {   // SW128, 128B rows
    return off ^ ((off >> 3) & 0x70);
}

// float <-> monotonic unsigned for atomicMax on floats
__device__ __forceinline__ unsigned encf(float f) {
    unsigned u = __float_as_uint(f);
    return (u >> 31) ? ~u : (u | 0x80000000u);
}
__device__ __forceinline__ float decf(unsigned e) {
    return __uint_as_float((e >> 31) ? (e & 0x7FFFFFFFu) : ~e);
}

// ---------------- kernel 1: R3-exact fused normalize ----------------
__global__ void __launch_bounds__(256) norm_kernel(const float* __restrict__ features) {
    __shared__ float4 sh[8];
    __shared__ float4 shr;

    int row = blockIdx.x;
    int t = threadIdx.x;   // one float4 per thread (1024/4 = 256)
    int w = t >> 5, l = t & 31;

    const float4* fo = (const float4*)(features + (size_t)row * DIM);
    const float4* fp = (const float4*)(features + (size_t)(row + BS) * DIM);
    const float4* fn = (const float4*)(features + (size_t)(row + 2 * BS) * DIM);
    float4 o = fo[t], p = fp[t], n = fn[t];

    float so = o.x*o.x + o.y*o.y + o.z*o.z + o.w*o.w;
    float sp = p.x*p.x + p.y*p.y + p.z*p.z + p.w*p.w;
    float sn = n.x*n.x + n.y*n.y + n.z*n.z + n.w*n.w;
    float dp = o.x*p.x + o.y*p.y + o.z*p.z + o.w*p.w;

    #pragma unroll
    for (int off = 16; off > 0; off >>= 1) {
        so += __shfl_xor_sync(0xFFFFFFFFu, so, off);
        sp += __shfl_xor_sync(0xFFFFFFFFu, sp, off);
        sn += __shfl_xor_sync(0xFFFFFFFFu, sn, off);
        dp += __shfl_xor_sync(0xFFFFFFFFu, dp, off);
    }
    if (l == 0) sh[w] = make_float4(so, sp, sn, dp);
    __syncthreads();
    if (w == 0) {
        float4 v = (l < 8) ? sh[l] : make_float4(0.f, 0.f, 0.f, 0.f);
        #pragma unroll
        for (int off = 4; off > 0; off >>= 1) {
            v.x += __shfl_xor_sync(0xFFFFFFFFu, v.x, off);
            v.y += __shfl_xor_sync(0xFFFFFFFFu, v.y, off);
            v.z += __shfl_xor_sync(0xFFFFFFFFu, v.z, off);
            v.w += __shfl_xor_sync(0xFFFFFFFFu, v.w, off);
        }
        if (l == 0) shr = v;
    }
    __syncthreads();
    float4 R = shr;

    float io  = 1.0f / fmaxf(sqrtf(R.x), 1e-12f);
    float ip  = 1.0f / fmaxf(sqrtf(R.y), 1e-12f);
    float in_ = 1.0f / fmaxf(sqrtf(R.z), 1e-12f);

    __half2* Ah = (__half2*)(g_A + (size_t)row * DIM);
    __half2* Nh = (__half2*)(g_Nn + (size_t)row * DIM);
    Ah[t * 2 + 0] = __floats2half2_rn(o.x*io, o.y*io);
    Ah[t * 2 + 1] = __floats2half2_rn(o.z*io, o.w*io);
    Nh[t * 2 + 0] = __floats2half2_rn(n.x*in_, n.y*in_);
    Nh[t * 2 + 1] = __floats2half2_rn(n.z*in_, n.w*in_);

    if (t == 0) {
        float cosap = R.w * io * ip;                 // a^ . p^
        g_pos[row] = (2.0f - 2.0f * cosap) * INV_T;
        g_rowmax[row] = 0u;   // < encoding of any finite float
        if (row == 0) g_done = 0u;   // reset completion counter (stream-ordered)
    }
}

// ---------------- kernel 2: GEMM + row-max + fused final reduction ----------------
__device__ __forceinline__ void load_chunk(uint32_t sA, uint32_t sB, int m0, int n0,
                                           int kc, int tid) {
    const __half* ga = g_A + (size_t)m0 * DIM + kc * BK;
    #pragma unroll
    for (int i = 0; i < 4; i++) {            // 128 rows * 8 segs / 256 thr = 4
        int seg = tid + i * 256;
        int r = seg >> 3, c8 = seg & 7;
        uint32_t off = (uint32_t)(r * 128 + c8 * 16);
        cp_async16(sA + swz(off), (const char*)ga + (size_t)r * (DIM * 2) + c8 * 16);
    }
    const __half* gb = g_Nn + (size_t)n0 * DIM + kc * BK;
    #pragma unroll
    for (int i = 0; i < 4; i++) {
        int seg = tid + i * 256;
        int r = seg >> 3, c8 = seg & 7;
        uint32_t off = (uint32_t)(r * 128 + c8 * 16);
        cp_async16(sB + swz(off), (const char*)gb + (size_t)r * (DIM * 2) + c8 * 16);
    }
}

__global__ void __launch_bounds__(256, 2) gemm_rowmax_kernel(float* __restrict__ out,
                                                             int out_size) {
    extern __shared__ char smem[];
    __shared__ unsigned s_rowmax[BM];
    __shared__ bool s_last;
    __shared__ float s_red[3][8];

    uint32_t base0 = smem_u32(smem);
    uint32_t data  = (base0 + 1023u) & ~1023u;   // align for swizzle pattern

    int tid = threadIdx.x;
    int wid = tid >> 5, lane = tid & 31;
    int wm = wid & 1, wn = wid >> 1;             // 2 M-warps x 4 N-warps
    int m0 = blockIdx.y * BM, n0 = blockIdx.x * BN;

    if (tid < BM) s_rowmax[tid] = 0u;

    // prologue: fill all 3 stages
    #pragma unroll
    for (int s = 0; s < NSTAGE; s++) {
        uint32_t st = data + s * STAGE_BYTES;
        load_chunk(st, st + A_ST, m0, n0, s, tid);
        CP_COMMIT();
    }

    float c[4][4][4];
    #pragma unroll
    for (int mi = 0; mi < 4; mi++)
        #pragma unroll
        for (int ni = 0; ni < 4; ni++)
            #pragma unroll
            for (int j = 0; j < 4; j++) c[mi][ni][j] = 0.0f;

    // per-lane ldmatrix address components
    int a_row = wm * 64 + (lane & 7) + ((lane & 8) ? 8 : 0);
    int a_kof = (lane & 16) ? 8 : 0;
    int b_rowbase = wn * 32 + (lane & 7) + ((lane & 8) ? 8 : 0);

    for (int k = 0; k < NKCH; k++) {
        uint32_t st = data + (k % NSTAGE) * STAGE_BYTES;
        uint32_t sA = st, sB = st + A_ST;
        CP_WAIT2();
        __syncthreads();

        #pragma unroll
        for (int kk = 0; kk < 4; kk++) {
            int kb = kk * 16;
            uint32_t a[4][4];
            #pragma unroll
            for (int mi = 0; mi < 4; mi++) {
                uint32_t off = (uint32_t)((a_row + mi * 16) * 128 + (kb + a_kof) * 2);
                ldsm_x4(sA + swz(off), a[mi][0], a[mi][1], a[mi][2], a[mi][3]);
            }
            uint32_t b[2][4];
            #pragma unroll
            for (int ni2 = 0; ni2 < 2; ni2++) {
                uint32_t off = (uint32_t)((b_rowbase + ni2 * 16) * 128 + (kb + a_kof) * 2);
                ldsm_x4(sB + swz(off), b[ni2][0], b[ni2][1], b[ni2][2], b[ni2][3]);
            }
            #pragma unroll
            for (int mi = 0; mi < 4; mi++) {
                #pragma unroll
                for (int ni = 0; ni < 4; ni++) {
                    int ni2 = ni >> 1, f = ni & 1;
                    mma16816(c[mi][ni], a[mi], b[ni2][f ? 1 : 0], b[ni2][f ? 3 : 2]);
                }
            }
        }

        __syncthreads();   // everyone done reading this stage
        if (k + NSTAGE < NKCH)
            load_chunk(sA, sB, m0, n0, k + NSTAGE, tid);
        CP_COMMIT();       // one group per iteration (may be empty)
    }

    // ---------- fused row-max epilogue ----------
    int gid = lane >> 2;       // 0..7 : row group within m16n8 frag
    int tig = lane & 3;
    #pragma unroll
    for (int mi = 0; mi < 4; mi++) {
        float mlo = -3.0e38f, mhi = -3.0e38f;
        #pragma unroll
        for (int ni = 0; ni < 4; ni++) {
            mlo = fmaxf(mlo, fmaxf(c[mi][ni][0], c[mi][ni][1]));
            mhi = fmaxf(mhi, fmaxf(c[mi][ni][2], c[mi][ni][3]));
        }
        mlo = fmaxf(mlo, __shfl_xor_sync(0xFFFFFFFFu, mlo, 1));
        mlo = fmaxf(mlo, __shfl_xor_sync(0xFFFFFFFFu, mlo, 2));
        mhi = fmaxf(mhi, __shfl_xor_sync(0xFFFFFFFFu, mhi, 1));
        mhi = fmaxf(mhi, __shfl_xor_sync(0xFFFFFFFFu, mhi, 2));
        if (tig == 0) {
            int rlo = wm * 64 + mi * 16 + gid;
            atomicMax(&s_rowmax[rlo], encf(mlo));
            atomicMax(&s_rowmax[rlo + 8], encf(mhi));
        }
    }
    __syncthreads();
    if (tid < BM) atomicMax(&g_rowmax[m0 + tid], s_rowmax[tid]);

    // ---------- last-CTA final reduction (threadfence-reduction pattern) ----------
    __syncthreads();
    if (tid == 0) {
        __threadfence();                                // publish our g_rowmax writes
        unsigned prev = atomicAdd(&g_done, 1u);
        s_last = (prev == TOTAL_CTAS - 1u);
    }
    __syncthreads();
    if (s_last) {
        float sl = 0.0f, sp = 0.0f, shd = 0.0f;
        for (int i = tid; i < BS; i += 256) {
            float md = decf(g_rowmax[i]);               // max dot for row i
            float hard = (2.0f - 2.0f * md) * INV_T;    // hardest negative distance
            float pos = g_pos[i];
            sl += fmaxf(MARGIN + pos - hard, 0.0f);
            sp += pos;
            shd += hard;
        }
        #pragma unroll
        for (int o = 16; o > 0; o >>= 1) {
            sl  += __shfl_xor_sync(0xFFFFFFFFu, sl, o);
            sp  += __shfl_xor_sync(0xFFFFFFFFu, sp, o);
            shd += __shfl_xor_sync(0xFFFFFFFFu, shd, o);
        }
        if (lane == 0) { s_red[0][wid] = sl; s_red[1][wid] = sp; s_red[2][wid] = shd; }
        __syncthreads();
        if (tid == 0) {
            float SL = 0.f, SP = 0.f, SH = 0.f;
            #pragma unroll
            for (int j = 0; j < 8; j++) {
                SL += s_red[0][j]; SP += s_red[1][j]; SH += s_red[2][j];
            }
            const float inv = 1.0f / (float)BS;
            if (out_size > 0) out[0] = SL * inv;
            if (out_size > 1) out[1] = SP * inv;
            if (out_size > 2) out[2] = SH * inv;
        }
    }
}

// ---------------- launch ----------------
extern "C" void kernel_launch(void* const* d_in, const int* in_sizes, int n_in,
                              void* d_out, int out_size) {
    const float* features = (const float*)d_in[0];
    float* out = (float*)d_out;

    cudaFuncSetAttribute(gemm_rowmax_kernel,
                         cudaFuncAttributeMaxDynamicSharedMemorySize, SMEM_TOTAL);

    norm_kernel<<<BS, 256>>>(features);

    dim3 grid(BS / BN, BS / BM);   // (64, 64) tiles
    gemm_rowmax_kernel<<<grid, 256, SMEM_TOTAL>>>(out, out_size);
}

// round 17
// speedup vs baseline: 1.0215x; 1.0215x over previous
#include <cuda_runtime.h>
#include <cuda_fp16.h>
#include <cstdint>
#include <cstddef>

// ---------------- problem constants ----------------
#define BS 8192
#define DIM 1024
#define INV_T 10.0f          // 1 / TEMPERATURE
#define MARGIN 1.0f          // max(0.01, 1.0 - 0.1*0.0)

// ---------------- GEMM tiling (R2 exact) ----------------
#define BM 128
#define BN 128
#define BK 64
#define NSTAGE 3
#define NKCH (DIM / BK)                 // 16 K-chunks
#define A_ST (BM * BK * 2)              // 16384 B / stage
#define B_ST (BN * BK * 2)              // 16384 B / stage
#define STAGE_BYTES (A_ST + B_ST)       // 32768
#define DATA_BYTES (STAGE_BYTES * NSTAGE)  // 98304
#define SMEM_TOTAL (DATA_BYTES + 1024)

// ---------------- device scratch (no allocation allowed) ----------------
__device__ __align__(16) __half   g_A[BS * DIM];     // normalized anchor, fp16
__device__ __align__(16) __half   g_Nn[BS * DIM];    // normalized negative, fp16
__device__ float    g_pos[BS];                       // positive distance / T
__device__ unsigned g_rowmax[BS];                    // encoded row-max of dot

// ---------------- helpers ----------------
__device__ __forceinline__ uint32_t smem_u32(const void* p) {
    uint32_t a;
    asm("{ .reg .u64 t; cvta.to.shared.u64 t, %1; cvt.u32.u64 %0, t; }"
        : "=r"(a) : "l"(p));
    return a;
}

__device__ __forceinline__ void cp_async16(uint32_t s, const void* g) {
    asm volatile("cp.async.cg.shared.global [%0], [%1], 16;" :: "r"(s), "l"(g));
}
#define CP_COMMIT() asm volatile("cp.async.commit_group;" ::: "memory")
#define CP_WAIT2()  asm volatile("cp.async.wait_group 2;" ::: "memory")

__device__ __forceinline__ void ldsm_x4(uint32_t addr, uint32_t& r0, uint32_t& r1,
                                        uint32_t& r2, uint32_t& r3) {
    asm volatile("ldmatrix.sync.aligned.m8n8.x4.shared.b16 {%0,%1,%2,%3}, [%4];"
                 : "=r"(r0), "=r"(r1), "=r"(r2), "=r"(r3) : "r"(addr));
}

__device__ __forceinline__ void mma16816(float* c, const uint32_t* a,
                                         uint32_t b0, uint32_t b1) {
    asm volatile(
        "mma.sync.aligned.m16n8k16.row.col.f32.f16.f16.f32 "
        "{%0,%1,%2,%3}, {%4,%5,%6,%7}, {%8,%9}, {%0,%1,%2,%3};"
        : "+f"(c[0]), "+f"(c[1]), "+f"(c[2]), "+f"(c[3])
        : "r"(a[0]), "r"(a[1]), "r"(a[2]), "r"(a[3]), "r"(b0), "r"(b1));
}

__device__ __forceinline__ uint32_t swz(uint32_t off) {   // SW128, 128B rows
    return off ^ ((off >> 3) & 0x70);
}

// float <-> monotonic unsigned for atomicMax on floats
__device__ __forceinline__ unsigned encf(float f) {
    unsigned u = __float_as_uint(f);
    return (u >> 31) ? ~u : (u | 0x80000000u);
}
__device__ __forceinline__ float decf(unsigned e) {
    return __uint_as_float((e >> 31) ? (e & 0x7FFFFFFFu) : ~e);
}

__device__ float blockReduce1024(float v) {  // 1024 threads, valid in thread 0
    __shared__ float sh[32];
    #pragma unroll
    for (int o = 16; o > 0; o >>= 1) v += __shfl_xor_sync(0xFFFFFFFFu, v, o);
    int w = threadIdx.x >> 5, l = threadIdx.x & 31;
    if (l == 0) sh[w] = v;
    __syncthreads();
    float r = 0.0f;
    if (w == 0) {
        r = sh[l];
        #pragma unroll
        for (int o = 16; o > 0; o >>= 1) r += __shfl_xor_sync(0xFFFFFFFFu, r, o);
    }
    __syncthreads();
    return r;
}

// ---------------- kernel 1: R3-exact fused normalize (best measured: 20.7 us) ----------------
__global__ void __launch_bounds__(256) norm_kernel(const float* __restrict__ features) {
    __shared__ float4 sh[8];
    __shared__ float4 shr;

    int row = blockIdx.x;
    int t = threadIdx.x;   // one float4 per thread (1024/4 = 256)
    int w = t >> 5, l = t & 31;

    const float4* fo = (const float4*)(features + (size_t)row * DIM);
    const float4* fp = (const float4*)(features + (size_t)(row + BS) * DIM);
    const float4* fn = (const float4*)(features + (size_t)(row + 2 * BS) * DIM);
    float4 o = fo[t], p = fp[t], n = fn[t];

    float so = o.x*o.x + o.y*o.y + o.z*o.z + o.w*o.w;
    float sp = p.x*p.x + p.y*p.y + p.z*p.z + p.w*p.w;
    float sn = n.x*n.x + n.y*n.y + n.z*n.z + n.w*n.w;
    float dp = o.x*p.x + o.y*p.y + o.z*p.z + o.w*p.w;

    #pragma unroll
    for (int off = 16; off > 0; off >>= 1) {
        so += __shfl_xor_sync(0xFFFFFFFFu, so, off);
        sp += __shfl_xor_sync(0xFFFFFFFFu, sp, off);
        sn += __shfl_xor_sync(0xFFFFFFFFu, sn, off);
        dp += __shfl_xor_sync(0xFFFFFFFFu, dp, off);
    }
    if (l == 0) sh[w] = make_float4(so, sp, sn, dp);
    __syncthreads();
    if (w == 0) {
        float4 v = (l < 8) ? sh[l] : make_float4(0.f, 0.f, 0.f, 0.f);
        #pragma unroll
        for (int off = 4; off > 0; off >>= 1) {
            v.x += __shfl_xor_sync(0xFFFFFFFFu, v.x, off);
            v.y += __shfl_xor_sync(0xFFFFFFFFu, v.y, off);
            v.z += __shfl_xor_sync(0xFFFFFFFFu, v.z, off);
            v.w += __shfl_xor_sync(0xFFFFFFFFu, v.w, off);
        }
        if (l == 0) shr = v;
    }
    __syncthreads();
    float4 R = shr;

    float io  = 1.0f / fmaxf(sqrtf(R.x), 1e-12f);
    float ip  = 1.0f / fmaxf(sqrtf(R.y), 1e-12f);
    float in_ = 1.0f / fmaxf(sqrtf(R.z), 1e-12f);

    __half2* Ah = (__half2*)(g_A + (size_t)row * DIM);
    __half2* Nh = (__half2*)(g_Nn + (size_t)row * DIM);
    Ah[t * 2 + 0] = __floats2half2_rn(o.x*io, o.y*io);
    Ah[t * 2 + 1] = __floats2half2_rn(o.z*io, o.w*io);
    Nh[t * 2 + 0] = __floats2half2_rn(n.x*in_, n.y*in_);
    Nh[t * 2 + 1] = __floats2half2_rn(n.z*in_, n.w*in_);

    if (t == 0) {
        float cosap = R.w * io * ip;                 // a^ . p^
        g_pos[row] = (2.0f - 2.0f * cosap) * INV_T;
        g_rowmax[row] = 0u;   // < encoding of any finite float
    }
}

// ---------------- kernel 2: fp16 mma.sync GEMM fused with row-max (R2 exact) ----------------
__device__ __forceinline__ void load_chunk(uint32_t sA, uint32_t sB, int m0, int n0,
                                           int kc, int tid) {
    const __half* ga = g_A + (size_t)m0 * DIM + kc * BK;
    #pragma unroll
    for (int i = 0; i < 4; i++) {            // 128 rows * 8 segs / 256 thr = 4
        int seg = tid + i * 256;
        int r = seg >> 3, c8 = seg & 7;
        uint32_t off = (uint32_t)(r * 128 + c8 * 16);
        cp_async16(sA + swz(off), (const char*)ga + (size_t)r * (DIM * 2) + c8 * 16);
    }
    const __half* gb = g_Nn + (size_t)n0 * DIM + kc * BK;
    #pragma unroll
    for (int i = 0; i < 4; i++) {
        int seg = tid + i * 256;
        int r = seg >> 3, c8 = seg & 7;
        uint32_t off = (uint32_t)(r * 128 + c8 * 16);
        cp_async16(sB + swz(off), (const char*)gb + (size_t)r * (DIM * 2) + c8 * 16);
    }
}

__global__ void __launch_bounds__(256, 2) gemm_rowmax_kernel() {
    extern __shared__ char smem[];
    __shared__ unsigned s_rowmax[BM];

    uint32_t base0 = smem_u32(smem);
    uint32_t data  = (base0 + 1023u) & ~1023u;   // align for swizzle pattern

    int tid = threadIdx.x;
    int wid = tid >> 5, lane = tid & 31;
    int wm = wid & 1, wn = wid >> 1;             // 2 M-warps x 4 N-warps
    int m0 = blockIdx.y * BM, n0 = blockIdx.x * BN;

    if (tid < BM) s_rowmax[tid] = 0u;

    // prologue: fill all 3 stages
    #pragma unroll
    for (int s = 0; s < NSTAGE; s++) {
        uint32_t st = data + s * STAGE_BYTES;
        load_chunk(st, st + A_ST, m0, n0, s, tid);
        CP_COMMIT();
    }

    float c[4][4][4];
    #pragma unroll
    for (int mi = 0; mi < 4; mi++)
        #pragma unroll
        for (int ni = 0; ni < 4; ni++)
            #pragma unroll
            for (int j = 0; j < 4; j++) c[mi][ni][j] = 0.0f;

    // per-lane ldmatrix address components
    int a_row = wm * 64 + (lane & 7) + ((lane & 8) ? 8 : 0);
    int a_kof = (lane & 16) ? 8 : 0;
    int b_rowbase = wn * 32 + (lane & 7) + ((lane & 8) ? 8 : 0);

    for (int k = 0; k < NKCH; k++) {
        uint32_t st = data + (k % NSTAGE) * STAGE_BYTES;
        uint32_t sA = st, sB = st + A_ST;
        CP_WAIT2();
        __syncthreads();

        #pragma unroll
        for (int kk = 0; kk < 4; kk++) {
            int kb = kk * 16;
            uint32_t a[4][4];
            #pragma unroll
            for (int mi = 0; mi < 4; mi++) {
                uint32_t off = (uint32_t)((a_row + mi * 16) * 128 + (kb + a_kof) * 2);
                ldsm_x4(sA + swz(off), a[mi][0], a[mi][1], a[mi][2], a[mi][3]);
            }
            uint32_t b[2][4];
            #pragma unroll
            for (int ni2 = 0; ni2 < 2; ni2++) {
                uint32_t off = (uint32_t)((b_rowbase + ni2 * 16) * 128 + (kb + a_kof) * 2);
                ldsm_x4(sB + swz(off), b[ni2][0], b[ni2][1], b[ni2][2], b[ni2][3]);
            }
            #pragma unroll
            for (int mi = 0; mi < 4; mi++) {
                #pragma unroll
                for (int ni = 0; ni < 4; ni++) {
                    int ni2 = ni >> 1, f = ni & 1;
                    mma16816(c[mi][ni], a[mi], b[ni2][f ? 1 : 0], b[ni2][f ? 3 : 2]);
                }
            }
        }

        __syncthreads();   // everyone done reading this stage
        if (k + NSTAGE < NKCH)
            load_chunk(sA, sB, m0, n0, k + NSTAGE, tid);
        CP_COMMIT();       // one group per iteration (may be empty)
    }

    // ---------- fused row-max epilogue ----------
    int gid = lane >> 2;       // 0..7 : row group within m16n8 frag
    int tig = lane & 3;
    #pragma unroll
    for (int mi = 0; mi < 4; mi++) {
        float mlo = -3.0e38f, mhi = -3.0e38f;
        #pragma unroll
        for (int ni = 0; ni < 4; ni++) {
            mlo = fmaxf(mlo, fmaxf(c[mi][ni][0], c[mi][ni][1]));
            mhi = fmaxf(mhi, fmaxf(c[mi][ni][2], c[mi][ni][3]));
        }
        mlo = fmaxf(mlo, __shfl_xor_sync(0xFFFFFFFFu, mlo, 1));
        mlo = fmaxf(mlo, __shfl_xor_sync(0xFFFFFFFFu, mlo, 2));
        mhi = fmaxf(mhi, __shfl_xor_sync(0xFFFFFFFFu, mhi, 1));
        mhi = fmaxf(mhi, __shfl_xor_sync(0xFFFFFFFFu, mhi, 2));
        if (tig == 0) {
            int rlo = wm * 64 + mi * 16 + gid;
            atomicMax(&s_rowmax[rlo], encf(mlo));
            atomicMax(&s_rowmax[rlo + 8], encf(mhi));
        }
    }
    __syncthreads();
    if (tid < BM) atomicMax(&g_rowmax[m0 + tid], s_rowmax[tid]);
}

// ---------------- kernel 3: final loss reduction ----------------
__global__ void __launch_bounds__(1024) finalize_kernel(float* __restrict__ out,
                                                        int out_size) {
    float sl = 0.0f, sp = 0.0f, sh = 0.0f;
    for (int i = threadIdx.x; i < BS; i += 1024) {
        float md = decf(g_rowmax[i]);                 // max dot for row i
        float hard = (2.0f - 2.0f * md) * INV_T;      // hardest negative distance
        float pos = g_pos[i];
        sl += fmaxf(MARGIN + pos - hard, 0.0f);
        sp += pos;
        sh += hard;
    }
    float SL = blockReduce1024(sl);
    float SP = blockReduce1024(sp);
    float SH = blockReduce1024(sh);
    if (threadIdx.x == 0) {
        const float inv = 1.0f / (float)BS;
        if (out_size > 0) out[0] = SL * inv;
        if (out_size > 1) out[1] = SP * inv;
        if (out_size > 2) out[2] = SH * inv;
    }
}

// ---------------- launch ----------------
extern "C" void kernel_launch(void* const* d_in, const int* in_sizes, int n_in,
                              void* d_out, int out_size) {
    const float* features = (const float*)d_in[0];
    float* out = (float*)d_out;

    cudaFuncSetAttribute(gemm_rowmax_kernel,
                         cudaFuncAttributeMaxDynamicSharedMemorySize, SMEM_TOTAL);

    norm_kernel<<<BS, 256>>>(features);

    dim3 grid(BS / BN, BS / BM);   // (64, 64) tiles
    gemm_rowmax_kernel<<<grid, 256, SMEM_TOTAL>>>();

    finalize_kernel<<<1, 1024>>>(out, out_size);
}